// round 16
// baseline (speedup 1.0000x reference)
#include <cuda_runtime.h>
#include <cuda_bf16.h>
#include <cuda_fp16.h>
#include <math.h>
#include <stdint.h>

// Problem constants
#define BB   2
#define TT   2048
#define CC   1024
#define HH   16
#define HD   64
#define HD2  32
#define MROWS (BB*TT)          // 4096
#define QKVW (3*CC)            // 3072

// Scratch (allocation-free rule: __device__ globals)
__device__ __half g_x16[(size_t)MROWS * CC];                // x fp16 [M][K]
__device__ __half g_o16[(size_t)MROWS * CC];                // attention out fp16 [M][K]
__device__ __half g_wq16[(size_t)QKVW * CC];                // Wqkv^T fp16 [N][K]
__device__ __half g_wp16[(size_t)CC * CC];                  // Wproj^T fp16 [N][K]
// Head-contiguous fp16 q (pre-scaled 1/8), k, v: [b*H+h][T][64]
#define HELEMS ((size_t)BB * HH * TT * HD)
__device__ __half g_q16[HELEMS], g_k16[HELEMS], g_v16[HELEMS];

// ---------------------------------------------------------------------------
// Helpers
// ---------------------------------------------------------------------------
__device__ __forceinline__ void ldsm_x4(unsigned r[4], unsigned addr)
{
    asm volatile("ldmatrix.sync.aligned.m8n8.x4.shared.b16 {%0,%1,%2,%3}, [%4];"
                 : "=r"(r[0]), "=r"(r[1]), "=r"(r[2]), "=r"(r[3]) : "r"(addr));
}

__device__ __forceinline__ void ldsm_x4_t(unsigned r[4], unsigned addr)
{
    asm volatile("ldmatrix.sync.aligned.m8n8.x4.trans.shared.b16 {%0,%1,%2,%3}, [%4];"
                 : "=r"(r[0]), "=r"(r[1]), "=r"(r[2]), "=r"(r[3]) : "r"(addr));
}

__device__ __forceinline__ void mma_fp16(float d[4], const unsigned a[4], unsigned b0, unsigned b1)
{
    asm volatile("mma.sync.aligned.m16n8k16.row.col.f32.f16.f16.f32 "
                 "{%0,%1,%2,%3}, {%4,%5,%6,%7}, {%8,%9}, {%0,%1,%2,%3};"
                 : "+f"(d[0]), "+f"(d[1]), "+f"(d[2]), "+f"(d[3])
                 : "r"(a[0]), "r"(a[1]), "r"(a[2]), "r"(a[3]), "r"(b0), "r"(b1));
}

__device__ __forceinline__ void cp16(unsigned dst, const void* src)
{
    asm volatile("cp.async.cg.shared.global [%0], [%1], 16;" :: "r"(dst), "l"(src));
}
#define CP_COMMIT  asm volatile("cp.async.commit_group;" ::: "memory")
#define CP_WAIT(n) asm volatile("cp.async.wait_group %0;" :: "n"(n) : "memory")

// ---------------------------------------------------------------------------
// Fused prep kernel: x->fp16  |  Wqkv transpose  |  Wproj transpose
// ---------------------------------------------------------------------------
__global__ __launch_bounds__(256) void prep_all(
    const float* __restrict__ X, __half* __restrict__ X16,
    const float* __restrict__ Wq, __half* __restrict__ Wq16,
    const float* __restrict__ Wp, __half* __restrict__ Wp16)
{
    __shared__ float tile[32][33];
    const int bx = blockIdx.x;

    if (bx < 4096) {
        int i = (bx * 256 + threadIdx.x) * 4;
        float4 v = *(const float4*)(X + i);
        __half2 a = __floats2half2_rn(v.x, v.y);
        __half2 b = __floats2half2_rn(v.z, v.w);
        *(uint2*)(X16 + i) = make_uint2(*(unsigned*)&a, *(unsigned*)&b);
        return;
    }

    const float* W; __half* Wt; int K, N, tb;
    if (bx < 7168) { W = Wq; Wt = Wq16; K = CC; N = QKVW; tb = bx - 4096; }
    else           { W = Wp; Wt = Wp16; K = CC; N = CC;   tb = bx - 7168; }
    const int nTiles = N / 32;
    const int n0 = (tb % nTiles) * 32, k0 = (tb / nTiles) * 32;
    const int tx = threadIdx.x & 31, ty = threadIdx.x >> 5;
    #pragma unroll
    for (int i = 0; i < 32; i += 8)
        tile[ty + i][tx] = W[(size_t)(k0 + ty + i) * N + n0 + tx];
    __syncthreads();
    #pragma unroll
    for (int i = 0; i < 32; i += 8)
        Wt[(size_t)(n0 + ty + i) * K + k0 + tx] = __float2half_rn(tile[tx][ty + i]);
}

// ---------------------------------------------------------------------------
// Shared GEMM mainloop: CTA 128x128, BK=64, 256 threads (8 warps 2x4,
// warp tile 64x32). fp16 single-pass, 3-stage cp.async ring, one barrier/chunk,
// register double-buffered fragments (ldsm for kc+1 overlaps MMAs of kc).
// ---------------------------------------------------------------------------
#define GROW   144                    // 64 fp16 = 128B + 16B pad (conflict-free)
#define GMAT   (128*GROW)             // 18432
#define GSTAGE (2*GMAT)               // 36864
#define GSMEM  (3*GSTAGE)             // 110592
#define EPSTR  132                    // epilogue staging stride (floats)
#define QKV_SMEM GSMEM

__device__ __forceinline__ void h_fill(
    unsigned sb,
    const __half* __restrict__ A_g, const __half* __restrict__ B_g,
    int row0, int col0, int K, int kbase, int tid)
{
    #pragma unroll
    for (int it = 0; it < 4; ++it) {
        int idx = it * 256 + tid;          // 0..1023
        int r = idx >> 3;                  // 0..127
        int c = idx & 7;                   // 16B chunk (8 per row)
        unsigned doff = (unsigned)(r * GROW + c * 16);
        cp16(sb + doff,        A_g + (size_t)(row0 + r) * K + kbase + c * 8);
        cp16(sb + GMAT + doff, B_g + (size_t)(col0 + r) * K + kbase + c * 8);
    }
}

__device__ __forceinline__ void h_frag_load(
    unsigned af[4][4], unsigned bf[2][4],
    unsigned sb, unsigned aoff, unsigned boff, int kc)
{
    #pragma unroll
    for (int n2 = 0; n2 < 2; ++n2)
        ldsm_x4(bf[n2], sb + boff + n2 * 16 * GROW + kc * 32);
    #pragma unroll
    for (int mi = 0; mi < 4; ++mi)
        ldsm_x4(af[mi], sb + aoff + mi * 16 * GROW + kc * 32);
}

__device__ __forceinline__ void h_mainloop(
    unsigned sb0, const __half* A_g, const __half* B_g,
    int row0, int col0, int K, int tid, float acc[4][4][4])
{
    const int lane = tid & 31;
    const int wid  = tid >> 5;
    const int wm   = wid >> 2;
    const int wn   = wid & 3;

    #pragma unroll
    for (int mi = 0; mi < 4; mi++)
        #pragma unroll
        for (int ni = 0; ni < 4; ni++)
            #pragma unroll
            for (int e = 0; e < 4; e++) acc[mi][ni][e] = 0.f;

    const int KT = K >> 6;   // 64-wide chunks

    h_fill(sb0,          A_g, B_g, row0, col0, K, 0,  tid); CP_COMMIT;
    h_fill(sb0 + GSTAGE, A_g, B_g, row0, col0, K, 64, tid); CP_COMMIT;

    const unsigned aoff = (unsigned)((wm * 64 + (lane & 15)) * GROW + (lane >> 4) * 16);
    const unsigned boff = (unsigned)(GMAT + (wn * 32 + (lane & 15)) * GROW + (lane >> 4) * 16);

    unsigned af[2][4][4], bf[2][2][4];   // double-buffered fragments

    unsigned stg = 0;
    for (int kt = 0; kt < KT; ++kt) {
        const unsigned sb = sb0 + stg;
        stg += GSTAGE; if (stg == GSMEM) stg = 0;

        const int rem = KT - 1 - kt;
        if (rem >= 1) CP_WAIT(1);
        else          CP_WAIT(0);
        __syncthreads();

        if (kt + 2 < KT) {
            unsigned nstg = stg + GSTAGE; if (nstg == GSMEM) nstg = 0;
            h_fill(sb0 + nstg, A_g, B_g, row0, col0, K, (kt + 2) * 64, tid);
            CP_COMMIT;
        }

        // preload kc=0 fragments
        h_frag_load(af[0], bf[0], sb, aoff, boff, 0);

        #pragma unroll
        for (int kc = 0; kc < 4; ++kc) {
            const int cur = kc & 1, nxt = cur ^ 1;
            if (kc < 3)
                h_frag_load(af[nxt], bf[nxt], sb, aoff, boff, kc + 1);
            #pragma unroll
            for (int mi = 0; mi < 4; ++mi)
                #pragma unroll
                for (int n2 = 0; n2 < 2; ++n2) {
                    mma_fp16(acc[mi][2 * n2],     af[cur][mi], bf[cur][n2][0], bf[cur][n2][2]);
                    mma_fp16(acc[mi][2 * n2 + 1], af[cur][mi], bf[cur][n2][1], bf[cur][n2][3]);
                }
        }
    }
}

// ---------------------------------------------------------------------------
// Proj GEMM: fp32 output + bias.
// ---------------------------------------------------------------------------
__global__ __launch_bounds__(256) void hgemm(
    const __half* __restrict__ A_g, const __half* __restrict__ B_g,
    const float* __restrict__ bias, float* __restrict__ Cm,
    int M, int N, int K)
{
    extern __shared__ __align__(16) char smem[];
    const unsigned sb0 = (unsigned)__cvta_generic_to_shared(smem);
    const int tid  = threadIdx.x;
    const int lane = tid & 31;
    const int wid  = tid >> 5;
    const int wm   = wid >> 2;
    const int wn   = wid & 3;
    const int row0 = blockIdx.y * 128;
    const int col0 = blockIdx.x * 128;

    float acc[4][4][4];
    h_mainloop(sb0, A_g, B_g, row0, col0, K, tid, acc);

    const int g  = lane >> 2;
    const int tq = lane & 3;
    #pragma unroll
    for (int mi = 0; mi < 4; mi++) {
        const int r0 = row0 + wm * 64 + mi * 16 + g;
        #pragma unroll
        for (int ni = 0; ni < 4; ni++) {
            const int c = col0 + wn * 32 + (ni >> 1) * 16 + (ni & 1) * 8 + tq * 2;
            const float bz0 = bias[c], bz1 = bias[c + 1];
            *(float2*)(Cm + (size_t)r0 * N + c) =
                make_float2(acc[mi][ni][0] + bz0, acc[mi][ni][1] + bz1);
            *(float2*)(Cm + (size_t)(r0 + 8) * N + c) =
                make_float2(acc[mi][ni][2] + bz0, acc[mi][ni][3] + bz1);
        }
    }
}

// ---------------------------------------------------------------------------
// QKV GEMM with fused bias + RoPE + fp16 epilogue.
// ---------------------------------------------------------------------------
__global__ __launch_bounds__(256) void hgemm_qkv(
    const __half* __restrict__ A_g, const __half* __restrict__ B_g,
    const float* __restrict__ bias,
    const float* __restrict__ cosf_, const float* __restrict__ sinf_,
    __half* __restrict__ q16, __half* __restrict__ k16,
    __half* __restrict__ v16, int K)
{
    extern __shared__ __align__(16) char smem[];
    const unsigned sb0 = (unsigned)__cvta_generic_to_shared(smem);
    const int tid  = threadIdx.x;
    const int lane = tid & 31;
    const int wid  = tid >> 5;
    const int wm   = wid >> 2;
    const int wn   = wid & 3;
    const int row0 = blockIdx.y * 128;
    const int col0 = blockIdx.x * 128;

    float acc[4][4][4];
    h_mainloop(sb0, A_g, B_g, row0, col0, K, tid, acc);

    const int g  = lane >> 2;
    const int tq = lane & 3;

    if (col0 >= 2 * CC) {
        const int hbase = (col0 - 2 * CC) >> 6;
        #pragma unroll
        for (int mi = 0; mi < 4; mi++) {
            #pragma unroll
            for (int ni = 0; ni < 4; ni++) {
                const int c = wn * 32 + (ni >> 1) * 16 + (ni & 1) * 8 + tq * 2;
                const int head = c >> 6, d = c & 63;
                const float bz0 = bias[col0 + c], bz1 = bias[col0 + c + 1];
                #pragma unroll
                for (int half_ = 0; half_ < 2; ++half_) {
                    const int row = row0 + wm * 64 + mi * 16 + g + half_ * 8;
                    const int b = row >> 11, t = row & (TT - 1);
                    const size_t dst = ((size_t)(b * HH + hbase + head) * TT + t) * HD + d;
                    *(__half2*)(v16 + dst) = __floats2half2_rn(
                        acc[mi][ni][2 * half_] + bz0, acc[mi][ni][2 * half_ + 1] + bz1);
                }
            }
        }
        return;
    }

    __syncthreads();
    float* sepi = (float*)smem;
    #pragma unroll
    for (int mi = 0; mi < 4; mi++) {
        const int r = wm * 64 + mi * 16 + g;
        #pragma unroll
        for (int ni = 0; ni < 4; ni++) {
            const int c = wn * 32 + (ni >> 1) * 16 + (ni & 1) * 8 + tq * 2;
            const float bz0 = bias[col0 + c], bz1 = bias[col0 + c + 1];
            sepi[r * EPSTR + c]           = acc[mi][ni][0] + bz0;
            sepi[r * EPSTR + c + 1]       = acc[mi][ni][1] + bz1;
            sepi[(r + 8) * EPSTR + c]     = acc[mi][ni][2] + bz0;
            sepi[(r + 8) * EPSTR + c + 1] = acc[mi][ni][3] + bz1;
        }
    }
    __syncthreads();

    {
        const bool isQ = (col0 < CC);
        const int hbase = (col0 & (CC - 1)) >> 6;
        __half* dstArr = isQ ? q16 : k16;
        const float qscale = isQ ? 0.125f : 1.0f;
        #pragma unroll
        for (int it = 0; it < 16; ++it) {
            int idx = it * 256 + tid;      // 0..4095
            int r   = idx >> 5;            // 0..127
            int pc  = idx & 31;
            int head = pc >> 4, d = (pc & 15) * 2;
            int c1 = head * 64 + d;
            int row = row0 + r;
            int b = row >> 11, t = row & (TT - 1);

            float2 va = *(float2*)&sepi[r * EPSTR + c1];
            float2 vb = *(float2*)&sepi[r * EPSTR + c1 + 32];
            float2 cs = *(const float2*)&cosf_[t * HD2 + d];
            float2 sn = *(const float2*)&sinf_[t * HD2 + d];

            __half2 o1 = __floats2half2_rn((va.x * cs.x - vb.x * sn.x) * qscale,
                                           (va.y * cs.y - vb.y * sn.y) * qscale);
            __half2 o2 = __floats2half2_rn((va.x * sn.x + vb.x * cs.x) * qscale,
                                           (va.y * sn.y + vb.y * cs.y) * qscale);

            size_t dst = ((size_t)(b * HH + hbase + head) * TT + t) * HD + d;
            *(__half2*)(dstArr + dst)       = o1;
            *(__half2*)(dstArr + dst + HD2) = o2;
        }
    }
}

// ---------------------------------------------------------------------------
// Flash attention, all-fp16 MMA. Br=64 (4 warps x 16 rows), Bc=64.
// 3-stage cp.async K/V ring with depth-2 prefetch.
// ---------------------------------------------------------------------------
#define KSTR2 144
#define ATT_K 0
#define ATT_V 9216
#define ATT_STAGE 18432
#define ATT_SMEM  (3*ATT_STAGE)       // 55296

__device__ __forceinline__ void att_fill(
    unsigned sb, const uint4* kp, const uint4* vp, int j0, int tid)
{
    const int base = j0 * 8;
    #pragma unroll
    for (int it = 0; it < 4; ++it) {
        int idx = it * 128 + tid;
        int r = idx >> 3, c16 = (idx & 7) * 16;
        unsigned doff = (unsigned)(r * KSTR2 + c16);
        cp16(sb + ATT_K + doff, kp + base + idx);
        cp16(sb + ATT_V + doff, vp + base + idx);
    }
}

__global__ __launch_bounds__(128) void attn_mma(
    const __half* __restrict__ q16_g, const __half* __restrict__ k16_g,
    const __half* __restrict__ v16_g, __half* __restrict__ o16_g)
{
    extern __shared__ __align__(16) char asm_raw[];
    const unsigned sb0 = (unsigned)__cvta_generic_to_shared(asm_raw);

    const int iTile = gridDim.x - 1 - blockIdx.x;   // heavy tiles first
    const int bh    = blockIdx.y;
    const int b = bh / HH, h = bh % HH;
    const int tid  = threadIdx.x;
    const int lane = tid & 31;
    const int wid  = tid >> 5;
    const int wr   = wid * 16;
    const int i0   = iTile * 64;
    const int g    = lane >> 2;
    const int tq   = lane & 3;

    const size_t hoff = (size_t)bh * TT * HD;

    {
        const uint4* qp = (const uint4*)(q16_g + hoff + (size_t)i0 * HD);
        char* smc = asm_raw;
        #pragma unroll
        for (int it = 0; it < 4; ++it) {
            int idx = it * 128 + tid;
            int r = idx >> 3, c16 = (idx & 7) * 16;
            *(uint4*)(smc + ATT_K + r * KSTR2 + c16) = qp[idx];
        }
    }
    __syncthreads();

    unsigned qf[4][4];
    {
        const unsigned aoffq = (unsigned)((wr + (lane & 15)) * KSTR2 + (lane >> 4) * 16);
        #pragma unroll
        for (int kc = 0; kc < 4; ++kc)
            ldsm_x4(qf[kc], sb0 + ATT_K + aoffq + kc * 32);
    }
    __syncthreads();

    float m0 = -INFINITY, m1 = -INFINITY, l0 = 0.f, l1 = 0.f;
    float o[8][4];
    #pragma unroll
    for (int ni = 0; ni < 8; ni++)
        #pragma unroll
        for (int e = 0; e < 4; e++) o[ni][e] = 0.f;

    const uint4* kp = (const uint4*)(k16_g + hoff);
    const uint4* vp = (const uint4*)(v16_g + hoff);

    att_fill(sb0, kp, vp, 0, tid);
    CP_COMMIT;
    if (iTile >= 1) {
        att_fill(sb0 + ATT_STAGE, kp, vp, 64, tid);
        CP_COMMIT;
    }

    unsigned stg = 0;
    for (int jT = 0; jT <= iTile; ++jT) {
        const int j0 = jT * 64;
        const unsigned sb = sb0 + stg;
        stg += ATT_STAGE; if (stg == ATT_SMEM) stg = 0;

        const int rem = iTile - jT;
        if (rem >= 1) CP_WAIT(1);
        else          CP_WAIT(0);
        __syncthreads();

        if (jT + 2 <= iTile) {
            unsigned nstg = stg + ATT_STAGE; if (nstg == ATT_SMEM) nstg = 0;
            att_fill(sb0 + nstg, kp, vp, j0 + 128, tid);
            CP_COMMIT;
        }

        float s[8][4];
        #pragma unroll
        for (int ni = 0; ni < 8; ni++)
            #pragma unroll
            for (int e = 0; e < 4; e++) s[ni][e] = 0.f;

        #pragma unroll
        for (int kc = 0; kc < 4; ++kc) {
            #pragma unroll
            for (int n2 = 0; n2 < 4; ++n2) {
                unsigned rk[4];
                const unsigned ad = (unsigned)((n2 * 16 + (lane & 15)) * KSTR2
                                               + (lane >> 4) * 16 + kc * 32);
                ldsm_x4(rk, sb + ATT_K + ad);
                mma_fp16(s[2 * n2],     qf[kc], rk[0], rk[2]);
                mma_fp16(s[2 * n2 + 1], qf[kc], rk[1], rk[3]);
            }
        }

        if (jT == iTile) {
            const int row0 = i0 + wr + g, row1 = row0 + 8;
            #pragma unroll
            for (int ni = 0; ni < 8; ++ni) {
                const int c0 = j0 + ni * 8 + tq * 2;
                if (c0 > row0)     s[ni][0] = -INFINITY;
                if (c0 + 1 > row0) s[ni][1] = -INFINITY;
                if (c0 > row1)     s[ni][2] = -INFINITY;
                if (c0 + 1 > row1) s[ni][3] = -INFINITY;
            }
        }

        float rm0 = -INFINITY, rm1 = -INFINITY;
        #pragma unroll
        for (int ni = 0; ni < 8; ++ni) {
            rm0 = fmaxf(rm0, fmaxf(s[ni][0], s[ni][1]));
            rm1 = fmaxf(rm1, fmaxf(s[ni][2], s[ni][3]));
        }
        rm0 = fmaxf(rm0, __shfl_xor_sync(0xffffffffu, rm0, 1));
        rm0 = fmaxf(rm0, __shfl_xor_sync(0xffffffffu, rm0, 2));
        rm1 = fmaxf(rm1, __shfl_xor_sync(0xffffffffu, rm1, 1));
        rm1 = fmaxf(rm1, __shfl_xor_sync(0xffffffffu, rm1, 2));

        const float mn0 = fmaxf(m0, rm0), mn1 = fmaxf(m1, rm1);
        const float al0 = __expf(m0 - mn0), al1 = __expf(m1 - mn1);
        m0 = mn0; m1 = mn1;

        unsigned pf[8][2];
        float sum0 = 0.f, sum1 = 0.f;
        #pragma unroll
        for (int ni = 0; ni < 8; ++ni) {
            float p0 = __expf(s[ni][0] - mn0);
            float p1 = __expf(s[ni][1] - mn0);
            float p2 = __expf(s[ni][2] - mn1);
            float p3 = __expf(s[ni][3] - mn1);
            sum0 += p0 + p1; sum1 += p2 + p3;
            __half2 h01 = __floats2half2_rn(p0, p1);
            __half2 h23 = __floats2half2_rn(p2, p3);
            pf[ni][0] = *(unsigned*)&h01;
            pf[ni][1] = *(unsigned*)&h23;
        }
        sum0 += __shfl_xor_sync(0xffffffffu, sum0, 1);
        sum0 += __shfl_xor_sync(0xffffffffu, sum0, 2);
        sum1 += __shfl_xor_sync(0xffffffffu, sum1, 1);
        sum1 += __shfl_xor_sync(0xffffffffu, sum1, 2);
        l0 = l0 * al0 + sum0;
        l1 = l1 * al1 + sum1;

        #pragma unroll
        for (int ni = 0; ni < 8; ++ni) {
            o[ni][0] *= al0; o[ni][1] *= al0;
            o[ni][2] *= al1; o[ni][3] *= al1;
        }

        #pragma unroll
        for (int kc = 0; kc < 4; ++kc) {
            unsigned ap[4] = { pf[2 * kc][0], pf[2 * kc][1], pf[2 * kc + 1][0], pf[2 * kc + 1][1] };
            #pragma unroll
            for (int n2 = 0; n2 < 4; ++n2) {
                unsigned v4[4];
                const unsigned ad = (unsigned)(ATT_V + (kc * 16 + (lane & 15)) * KSTR2
                                               + (n2 * 2 + (lane >> 4)) * 16);
                ldsm_x4_t(v4, sb + ad);
                mma_fp16(o[2 * n2],     ap, v4[0], v4[1]);
                mma_fp16(o[2 * n2 + 1], ap, v4[2], v4[3]);
            }
        }
    }

    const float inv0 = 1.f / l0, inv1 = 1.f / l1;
    const int row0 = i0 + wr + g;
    #pragma unroll
    for (int ni = 0; ni < 8; ++ni) {
        const int col = h * HD + ni * 8 + tq * 2;
        const size_t i0a = (size_t)(b * TT + row0) * CC + col;
        const size_t i1a = (size_t)(b * TT + row0 + 8) * CC + col;
        __half2 v0 = __floats2half2_rn(o[ni][0] * inv0, o[ni][1] * inv0);
        __half2 v1 = __floats2half2_rn(o[ni][2] * inv1, o[ni][3] * inv1);
        *(__half2*)(o16_g + i0a) = v0;
        *(__half2*)(o16_g + i1a) = v1;
    }
}

// ---------------------------------------------------------------------------
// Launch
// ---------------------------------------------------------------------------
extern "C" void kernel_launch(void* const* d_in, const int* in_sizes, int n_in,
                              void* d_out, int out_size)
{
    const float* x     = (const float*)d_in[0];
    const float* fcos  = (const float*)d_in[1];
    const float* fsin  = (const float*)d_in[2];
    const float* Wqkv  = (const float*)d_in[3];
    const float* bqkv  = (const float*)d_in[4];
    const float* Wproj = (const float*)d_in[5];
    const float* bproj = (const float*)d_in[6];
    float* out = (float*)d_out;

    __half *x16, *o16, *wq16, *wp16, *q16, *k16, *v16;
    cudaGetSymbolAddress((void**)&x16, g_x16);
    cudaGetSymbolAddress((void**)&o16, g_o16);
    cudaGetSymbolAddress((void**)&wq16, g_wq16);
    cudaGetSymbolAddress((void**)&wp16, g_wp16);
    cudaGetSymbolAddress((void**)&q16, g_q16);
    cudaGetSymbolAddress((void**)&k16, g_k16);
    cudaGetSymbolAddress((void**)&v16, g_v16);

    cudaFuncSetAttribute(hgemm, cudaFuncAttributeMaxDynamicSharedMemorySize, GSMEM);
    cudaFuncSetAttribute(hgemm_qkv, cudaFuncAttributeMaxDynamicSharedMemorySize, QKV_SMEM);
    cudaFuncSetAttribute(attn_mma, cudaFuncAttributeMaxDynamicSharedMemorySize, ATT_SMEM);

    // 0) fused prep
    prep_all<<<8192, 256>>>(x, x16, Wqkv, wq16, Wproj, wp16);

    // 1) QKV GEMM with fused bias+RoPE epilogue -> fp16 q/k/v
    {
        dim3 grid(QKVW / 128, MROWS / 128);   // (24, 32)
        hgemm_qkv<<<grid, 256, QKV_SMEM>>>(x16, wq16, bqkv, fcos, fsin,
                                           q16, k16, v16, CC);
    }
    // 2) Flash attention (Br=64, 3-stage ring) -> fp16 att
    {
        dim3 grid(TT / 64, BB * HH);          // (32, 32)
        attn_mma<<<grid, 128, ATT_SMEM>>>(q16, k16, v16, o16);
    }
    // 3) out = att @ Wproj + bproj
    {
        dim3 grid(CC / 128, MROWS / 128);     // (8, 32)
        hgemm<<<grid, 256, GSMEM>>>(o16, wp16, bproj, out, MROWS, CC, CC);
    }
}

// round 17
// speedup vs baseline: 1.0782x; 1.0782x over previous
#include <cuda_runtime.h>
#include <cuda_bf16.h>
#include <cuda_fp16.h>
#include <math.h>
#include <stdint.h>

// Problem constants
#define BB   2
#define TT   2048
#define CC   1024
#define HH   16
#define HD   64
#define HD2  32
#define MROWS (BB*TT)          // 4096
#define QKVW (3*CC)            // 3072

// Scratch (allocation-free rule: __device__ globals)
__device__ __half g_x16[(size_t)MROWS * CC];                // x fp16 [M][K]
__device__ __half g_o16[(size_t)MROWS * CC];                // attention out fp16 [M][K]
__device__ __half g_wq16[(size_t)QKVW * CC];                // Wqkv^T fp16 [N][K]
__device__ __half g_wp16[(size_t)CC * CC];                  // Wproj^T fp16 [N][K]
// Head-contiguous fp16 q (pre-scaled log2e/8), k, v: [b*H+h][T][64]
#define HELEMS ((size_t)BB * HH * TT * HD)
__device__ __half g_q16[HELEMS], g_k16[HELEMS], g_v16[HELEMS];

// ---------------------------------------------------------------------------
// Helpers
// ---------------------------------------------------------------------------
__device__ __forceinline__ void ldsm_x4(unsigned r[4], unsigned addr)
{
    asm volatile("ldmatrix.sync.aligned.m8n8.x4.shared.b16 {%0,%1,%2,%3}, [%4];"
                 : "=r"(r[0]), "=r"(r[1]), "=r"(r[2]), "=r"(r[3]) : "r"(addr));
}

__device__ __forceinline__ void ldsm_x4_t(unsigned r[4], unsigned addr)
{
    asm volatile("ldmatrix.sync.aligned.m8n8.x4.trans.shared.b16 {%0,%1,%2,%3}, [%4];"
                 : "=r"(r[0]), "=r"(r[1]), "=r"(r[2]), "=r"(r[3]) : "r"(addr));
}

__device__ __forceinline__ void mma_fp16(float d[4], const unsigned a[4], unsigned b0, unsigned b1)
{
    asm volatile("mma.sync.aligned.m16n8k16.row.col.f32.f16.f16.f32 "
                 "{%0,%1,%2,%3}, {%4,%5,%6,%7}, {%8,%9}, {%0,%1,%2,%3};"
                 : "+f"(d[0]), "+f"(d[1]), "+f"(d[2]), "+f"(d[3])
                 : "r"(a[0]), "r"(a[1]), "r"(a[2]), "r"(a[3]), "r"(b0), "r"(b1));
}

__device__ __forceinline__ void cp16(unsigned dst, const void* src)
{
    asm volatile("cp.async.cg.shared.global [%0], [%1], 16;" :: "r"(dst), "l"(src));
}
#define CP_COMMIT  asm volatile("cp.async.commit_group;" ::: "memory")
#define CP_WAIT(n) asm volatile("cp.async.wait_group %0;" :: "n"(n) : "memory")

// pure MUFU.EX2
__device__ __forceinline__ float ex2(float x)
{
    float r;
    asm("ex2.approx.ftz.f32 %0, %1;" : "=f"(r) : "f"(x));
    return r;
}

// ---------------------------------------------------------------------------
// Fused prep kernel: x->fp16  |  Wqkv transpose  |  Wproj transpose
// ---------------------------------------------------------------------------
__global__ __launch_bounds__(256) void prep_all(
    const float* __restrict__ X, __half* __restrict__ X16,
    const float* __restrict__ Wq, __half* __restrict__ Wq16,
    const float* __restrict__ Wp, __half* __restrict__ Wp16)
{
    __shared__ float tile[32][33];
    const int bx = blockIdx.x;

    if (bx < 4096) {
        int i = (bx * 256 + threadIdx.x) * 4;
        float4 v = *(const float4*)(X + i);
        __half2 a = __floats2half2_rn(v.x, v.y);
        __half2 b = __floats2half2_rn(v.z, v.w);
        *(uint2*)(X16 + i) = make_uint2(*(unsigned*)&a, *(unsigned*)&b);
        return;
    }

    const float* W; __half* Wt; int K, N, tb;
    if (bx < 7168) { W = Wq; Wt = Wq16; K = CC; N = QKVW; tb = bx - 4096; }
    else           { W = Wp; Wt = Wp16; K = CC; N = CC;   tb = bx - 7168; }
    const int nTiles = N / 32;
    const int n0 = (tb % nTiles) * 32, k0 = (tb / nTiles) * 32;
    const int tx = threadIdx.x & 31, ty = threadIdx.x >> 5;
    #pragma unroll
    for (int i = 0; i < 32; i += 8)
        tile[ty + i][tx] = W[(size_t)(k0 + ty + i) * N + n0 + tx];
    __syncthreads();
    #pragma unroll
    for (int i = 0; i < 32; i += 8)
        Wt[(size_t)(n0 + ty + i) * K + k0 + tx] = __float2half_rn(tile[tx][ty + i]);
}

// ---------------------------------------------------------------------------
// Shared GEMM mainloop: CTA 128x128, BK=64, 256 threads (8 warps 2x4,
// warp tile 64x32). fp16 single-pass, 3-stage cp.async ring, one barrier/chunk.
// ---------------------------------------------------------------------------
#define GROW   144                    // 64 fp16 = 128B + 16B pad (conflict-free)
#define GMAT   (128*GROW)             // 18432
#define GSTAGE (2*GMAT)               // 36864
#define GSMEM  (3*GSTAGE)             // 110592
#define EPSTR  132                    // epilogue staging stride (floats)
#define QKV_SMEM GSMEM

__device__ __forceinline__ void h_fill(
    unsigned sb,
    const __half* __restrict__ A_g, const __half* __restrict__ B_g,
    int row0, int col0, int K, int kbase, int tid)
{
    #pragma unroll
    for (int it = 0; it < 4; ++it) {
        int idx = it * 256 + tid;          // 0..1023
        int r = idx >> 3;                  // 0..127
        int c = idx & 7;                   // 16B chunk (8 per row)
        unsigned doff = (unsigned)(r * GROW + c * 16);
        cp16(sb + doff,        A_g + (size_t)(row0 + r) * K + kbase + c * 8);
        cp16(sb + GMAT + doff, B_g + (size_t)(col0 + r) * K + kbase + c * 8);
    }
}

__device__ __forceinline__ void h_mainloop(
    unsigned sb0, const __half* A_g, const __half* B_g,
    int row0, int col0, int K, int tid, float acc[4][4][4])
{
    const int lane = tid & 31;
    const int wid  = tid >> 5;
    const int wm   = wid >> 2;
    const int wn   = wid & 3;

    #pragma unroll
    for (int mi = 0; mi < 4; mi++)
        #pragma unroll
        for (int ni = 0; ni < 4; ni++)
            #pragma unroll
            for (int e = 0; e < 4; e++) acc[mi][ni][e] = 0.f;

    const int KT = K >> 6;   // 64-wide chunks

    h_fill(sb0,          A_g, B_g, row0, col0, K, 0,  tid); CP_COMMIT;
    h_fill(sb0 + GSTAGE, A_g, B_g, row0, col0, K, 64, tid); CP_COMMIT;

    const unsigned aoff = (unsigned)((wm * 64 + (lane & 15)) * GROW + (lane >> 4) * 16);
    const unsigned boff = (unsigned)(GMAT + (wn * 32 + (lane & 15)) * GROW + (lane >> 4) * 16);

    unsigned stg = 0;
    for (int kt = 0; kt < KT; ++kt) {
        const unsigned sb = sb0 + stg;
        stg += GSTAGE; if (stg == GSMEM) stg = 0;

        const int rem = KT - 1 - kt;
        if (rem >= 1) CP_WAIT(1);
        else          CP_WAIT(0);
        __syncthreads();

        if (kt + 2 < KT) {
            unsigned nstg = stg + GSTAGE; if (nstg == GSMEM) nstg = 0;
            h_fill(sb0 + nstg, A_g, B_g, row0, col0, K, (kt + 2) * 64, tid);
            CP_COMMIT;
        }

        #pragma unroll
        for (int kc = 0; kc < 4; ++kc) {
            unsigned af[4][4], bf[2][4];
            #pragma unroll
            for (int n2 = 0; n2 < 2; ++n2)
                ldsm_x4(bf[n2], sb + boff + n2 * 16 * GROW + kc * 32);
            #pragma unroll
            for (int mi = 0; mi < 4; ++mi)
                ldsm_x4(af[mi], sb + aoff + mi * 16 * GROW + kc * 32);
            #pragma unroll
            for (int mi = 0; mi < 4; ++mi)
                #pragma unroll
                for (int n2 = 0; n2 < 2; ++n2) {
                    mma_fp16(acc[mi][2 * n2],     af[mi], bf[n2][0], bf[n2][2]);
                    mma_fp16(acc[mi][2 * n2 + 1], af[mi], bf[n2][1], bf[n2][3]);
                }
        }
    }
}

// ---------------------------------------------------------------------------
// Proj GEMM: fp32 output + bias.
// ---------------------------------------------------------------------------
__global__ __launch_bounds__(256) void hgemm(
    const __half* __restrict__ A_g, const __half* __restrict__ B_g,
    const float* __restrict__ bias, float* __restrict__ Cm,
    int M, int N, int K)
{
    extern __shared__ __align__(16) char smem[];
    const unsigned sb0 = (unsigned)__cvta_generic_to_shared(smem);
    const int tid  = threadIdx.x;
    const int lane = tid & 31;
    const int wid  = tid >> 5;
    const int wm   = wid >> 2;
    const int wn   = wid & 3;
    const int row0 = blockIdx.y * 128;
    const int col0 = blockIdx.x * 128;

    float acc[4][4][4];
    h_mainloop(sb0, A_g, B_g, row0, col0, K, tid, acc);

    const int g  = lane >> 2;
    const int tq = lane & 3;
    #pragma unroll
    for (int mi = 0; mi < 4; mi++) {
        const int r0 = row0 + wm * 64 + mi * 16 + g;
        #pragma unroll
        for (int ni = 0; ni < 4; ni++) {
            const int c = col0 + wn * 32 + (ni >> 1) * 16 + (ni & 1) * 8 + tq * 2;
            const float bz0 = bias[c], bz1 = bias[c + 1];
            *(float2*)(Cm + (size_t)r0 * N + c) =
                make_float2(acc[mi][ni][0] + bz0, acc[mi][ni][1] + bz1);
            *(float2*)(Cm + (size_t)(r0 + 8) * N + c) =
                make_float2(acc[mi][ni][2] + bz0, acc[mi][ni][3] + bz1);
        }
    }
}

// ---------------------------------------------------------------------------
// QKV GEMM with fused bias + RoPE + fp16 epilogue.
// q pre-scaled by log2(e)/8 so attention softmax can use exp2 directly.
// ---------------------------------------------------------------------------
#define QSCALE 0.18033688f    // log2(e) / 8

__global__ __launch_bounds__(256) void hgemm_qkv(
    const __half* __restrict__ A_g, const __half* __restrict__ B_g,
    const float* __restrict__ bias,
    const float* __restrict__ cosf_, const float* __restrict__ sinf_,
    __half* __restrict__ q16, __half* __restrict__ k16,
    __half* __restrict__ v16, int K)
{
    extern __shared__ __align__(16) char smem[];
    const unsigned sb0 = (unsigned)__cvta_generic_to_shared(smem);
    const int tid  = threadIdx.x;
    const int lane = tid & 31;
    const int wid  = tid >> 5;
    const int wm   = wid >> 2;
    const int wn   = wid & 3;
    const int row0 = blockIdx.y * 128;
    const int col0 = blockIdx.x * 128;

    float acc[4][4][4];
    h_mainloop(sb0, A_g, B_g, row0, col0, K, tid, acc);

    const int g  = lane >> 2;
    const int tq = lane & 3;

    if (col0 >= 2 * CC) {
        const int hbase = (col0 - 2 * CC) >> 6;
        #pragma unroll
        for (int mi = 0; mi < 4; mi++) {
            #pragma unroll
            for (int ni = 0; ni < 4; ni++) {
                const int c = wn * 32 + (ni >> 1) * 16 + (ni & 1) * 8 + tq * 2;
                const int head = c >> 6, d = c & 63;
                const float bz0 = bias[col0 + c], bz1 = bias[col0 + c + 1];
                #pragma unroll
                for (int half_ = 0; half_ < 2; ++half_) {
                    const int row = row0 + wm * 64 + mi * 16 + g + half_ * 8;
                    const int b = row >> 11, t = row & (TT - 1);
                    const size_t dst = ((size_t)(b * HH + hbase + head) * TT + t) * HD + d;
                    *(__half2*)(v16 + dst) = __floats2half2_rn(
                        acc[mi][ni][2 * half_] + bz0, acc[mi][ni][2 * half_ + 1] + bz1);
                }
            }
        }
        return;
    }

    __syncthreads();
    float* sepi = (float*)smem;
    #pragma unroll
    for (int mi = 0; mi < 4; mi++) {
        const int r = wm * 64 + mi * 16 + g;
        #pragma unroll
        for (int ni = 0; ni < 4; ni++) {
            const int c = wn * 32 + (ni >> 1) * 16 + (ni & 1) * 8 + tq * 2;
            const float bz0 = bias[col0 + c], bz1 = bias[col0 + c + 1];
            sepi[r * EPSTR + c]           = acc[mi][ni][0] + bz0;
            sepi[r * EPSTR + c + 1]       = acc[mi][ni][1] + bz1;
            sepi[(r + 8) * EPSTR + c]     = acc[mi][ni][2] + bz0;
            sepi[(r + 8) * EPSTR + c + 1] = acc[mi][ni][3] + bz1;
        }
    }
    __syncthreads();

    {
        const bool isQ = (col0 < CC);
        const int hbase = (col0 & (CC - 1)) >> 6;
        __half* dstArr = isQ ? q16 : k16;
        const float qscale = isQ ? QSCALE : 1.0f;
        #pragma unroll
        for (int it = 0; it < 16; ++it) {
            int idx = it * 256 + tid;      // 0..4095
            int r   = idx >> 5;            // 0..127
            int pc  = idx & 31;
            int head = pc >> 4, d = (pc & 15) * 2;
            int c1 = head * 64 + d;
            int row = row0 + r;
            int b = row >> 11, t = row & (TT - 1);

            float2 va = *(float2*)&sepi[r * EPSTR + c1];
            float2 vb = *(float2*)&sepi[r * EPSTR + c1 + 32];
            float2 cs = *(const float2*)&cosf_[t * HD2 + d];
            float2 sn = *(const float2*)&sinf_[t * HD2 + d];

            __half2 o1 = __floats2half2_rn((va.x * cs.x - vb.x * sn.x) * qscale,
                                           (va.y * cs.y - vb.y * sn.y) * qscale);
            __half2 o2 = __floats2half2_rn((va.x * sn.x + vb.x * cs.x) * qscale,
                                           (va.y * sn.y + vb.y * cs.y) * qscale);

            size_t dst = ((size_t)(b * HH + hbase + head) * TT + t) * HD + d;
            *(__half2*)(dstArr + dst)       = o1;
            *(__half2*)(dstArr + dst + HD2) = o2;
        }
    }
}

// ---------------------------------------------------------------------------
// Flash attention, all-fp16 MMA, base-2 softmax (scores already in log2 units).
// Br=64 (4 warps x 16 rows), Bc=64. cp.async double-buffered K/V.
// ---------------------------------------------------------------------------
#define KSTR2 144
#define ATT_K 0
#define ATT_V 9216
#define ATT_STAGE 18432
#define ATT_SMEM  (2*ATT_STAGE)

__device__ __forceinline__ void att_fill(
    unsigned sb, const uint4* kp, const uint4* vp, int j0, int tid)
{
    const int base = j0 * 8;
    #pragma unroll
    for (int it = 0; it < 4; ++it) {
        int idx = it * 128 + tid;
        int r = idx >> 3, c16 = (idx & 7) * 16;
        unsigned doff = (unsigned)(r * KSTR2 + c16);
        cp16(sb + ATT_K + doff, kp + base + idx);
        cp16(sb + ATT_V + doff, vp + base + idx);
    }
}

__global__ __launch_bounds__(128) void attn_mma(
    const __half* __restrict__ q16_g, const __half* __restrict__ k16_g,
    const __half* __restrict__ v16_g, __half* __restrict__ o16_g)
{
    extern __shared__ __align__(16) char asm_raw[];
    const unsigned sb0 = (unsigned)__cvta_generic_to_shared(asm_raw);

    const int iTile = gridDim.x - 1 - blockIdx.x;   // heavy tiles first
    const int bh    = blockIdx.y;
    const int b = bh / HH, h = bh % HH;
    const int tid  = threadIdx.x;
    const int lane = tid & 31;
    const int wid  = tid >> 5;
    const int wr   = wid * 16;
    const int i0   = iTile * 64;
    const int g    = lane >> 2;
    const int tq   = lane & 3;

    const size_t hoff = (size_t)bh * TT * HD;

    // stage Q through smem, ldmatrix to registers
    {
        const uint4* qp = (const uint4*)(q16_g + hoff + (size_t)i0 * HD);
        char* smc = asm_raw;
        #pragma unroll
        for (int it = 0; it < 4; ++it) {
            int idx = it * 128 + tid;
            int r = idx >> 3, c16 = (idx & 7) * 16;
            *(uint4*)(smc + ATT_K + r * KSTR2 + c16) = qp[idx];
        }
    }
    __syncthreads();

    unsigned qf[4][4];
    {
        const unsigned aoffq = (unsigned)((wr + (lane & 15)) * KSTR2 + (lane >> 4) * 16);
        #pragma unroll
        for (int kc = 0; kc < 4; ++kc)
            ldsm_x4(qf[kc], sb0 + ATT_K + aoffq + kc * 32);
    }
    __syncthreads();   // Q frags read before stage-0 fill overwrites

    float m0 = -INFINITY, m1 = -INFINITY, l0 = 0.f, l1 = 0.f;
    float o[8][4];
    #pragma unroll
    for (int ni = 0; ni < 8; ni++)
        #pragma unroll
        for (int e = 0; e < 4; e++) o[ni][e] = 0.f;

    const uint4* kp = (const uint4*)(k16_g + hoff);
    const uint4* vp = (const uint4*)(v16_g + hoff);

    att_fill(sb0, kp, vp, 0, tid);
    CP_COMMIT;

    for (int jT = 0; jT <= iTile; ++jT) {
        const int j0 = jT * 64;
        const unsigned sb = sb0 + (unsigned)(jT & 1) * ATT_STAGE;

        CP_WAIT(0);
        __syncthreads();

        if (jT < iTile) {
            att_fill(sb0 + (unsigned)((jT + 1) & 1) * ATT_STAGE, kp, vp, j0 + 64, tid);
            CP_COMMIT;
        }

        // ---- S = Q K^T (single-pass fp16; scores in log2 units) ----
        float s[8][4];
        #pragma unroll
        for (int ni = 0; ni < 8; ni++)
            #pragma unroll
            for (int e = 0; e < 4; e++) s[ni][e] = 0.f;

        #pragma unroll
        for (int kc = 0; kc < 4; ++kc) {
            #pragma unroll
            for (int n2 = 0; n2 < 4; ++n2) {
                unsigned rk[4];
                const unsigned ad = (unsigned)((n2 * 16 + (lane & 15)) * KSTR2
                                               + (lane >> 4) * 16 + kc * 32);
                ldsm_x4(rk, sb + ATT_K + ad);
                mma_fp16(s[2 * n2],     qf[kc], rk[0], rk[2]);
                mma_fp16(s[2 * n2 + 1], qf[kc], rk[1], rk[3]);
            }
        }

        if (jT == iTile) {
            const int row0 = i0 + wr + g, row1 = row0 + 8;
            #pragma unroll
            for (int ni = 0; ni < 8; ++ni) {
                const int c0 = j0 + ni * 8 + tq * 2;
                if (c0 > row0)     s[ni][0] = -INFINITY;
                if (c0 + 1 > row0) s[ni][1] = -INFINITY;
                if (c0 > row1)     s[ni][2] = -INFINITY;
                if (c0 + 1 > row1) s[ni][3] = -INFINITY;
            }
        }

        // ---- online softmax (base 2) ----
        float rm0 = -INFINITY, rm1 = -INFINITY;
        #pragma unroll
        for (int ni = 0; ni < 8; ++ni) {
            rm0 = fmaxf(rm0, fmaxf(s[ni][0], s[ni][1]));
            rm1 = fmaxf(rm1, fmaxf(s[ni][2], s[ni][3]));
        }
        rm0 = fmaxf(rm0, __shfl_xor_sync(0xffffffffu, rm0, 1));
        rm0 = fmaxf(rm0, __shfl_xor_sync(0xffffffffu, rm0, 2));
        rm1 = fmaxf(rm1, __shfl_xor_sync(0xffffffffu, rm1, 1));
        rm1 = fmaxf(rm1, __shfl_xor_sync(0xffffffffu, rm1, 2));

        const float mn0 = fmaxf(m0, rm0), mn1 = fmaxf(m1, rm1);
        const float al0 = ex2(m0 - mn0), al1 = ex2(m1 - mn1);
        m0 = mn0; m1 = mn1;

        unsigned pf[8][2];
        float sum0 = 0.f, sum1 = 0.f;
        #pragma unroll
        for (int ni = 0; ni < 8; ++ni) {
            float p0 = ex2(s[ni][0] - mn0);
            float p1 = ex2(s[ni][1] - mn0);
            float p2 = ex2(s[ni][2] - mn1);
            float p3 = ex2(s[ni][3] - mn1);
            sum0 += p0 + p1; sum1 += p2 + p3;
            __half2 h01 = __floats2half2_rn(p0, p1);
            __half2 h23 = __floats2half2_rn(p2, p3);
            pf[ni][0] = *(unsigned*)&h01;
            pf[ni][1] = *(unsigned*)&h23;
        }
        sum0 += __shfl_xor_sync(0xffffffffu, sum0, 1);
        sum0 += __shfl_xor_sync(0xffffffffu, sum0, 2);
        sum1 += __shfl_xor_sync(0xffffffffu, sum1, 1);
        sum1 += __shfl_xor_sync(0xffffffffu, sum1, 2);
        l0 = l0 * al0 + sum0;
        l1 = l1 * al1 + sum1;

        #pragma unroll
        for (int ni = 0; ni < 8; ++ni) {
            o[ni][0] *= al0; o[ni][1] *= al0;
            o[ni][2] *= al1; o[ni][3] *= al1;
        }

        // ---- O += P V (single-pass fp16) ----
        #pragma unroll
        for (int kc = 0; kc < 4; ++kc) {
            unsigned ap[4] = { pf[2 * kc][0], pf[2 * kc][1], pf[2 * kc + 1][0], pf[2 * kc + 1][1] };
            #pragma unroll
            for (int n2 = 0; n2 < 4; ++n2) {
                unsigned v4[4];
                const unsigned ad = (unsigned)(ATT_V + (kc * 16 + (lane & 15)) * KSTR2
                                               + (n2 * 2 + (lane >> 4)) * 16);
                ldsm_x4_t(v4, sb + ad);
                mma_fp16(o[2 * n2],     ap, v4[0], v4[1]);
                mma_fp16(o[2 * n2 + 1], ap, v4[2], v4[3]);
            }
        }
    }

    const float inv0 = 1.f / l0, inv1 = 1.f / l1;
    const int row0 = i0 + wr + g;
    #pragma unroll
    for (int ni = 0; ni < 8; ++ni) {
        const int col = h * HD + ni * 8 + tq * 2;
        const size_t i0a = (size_t)(b * TT + row0) * CC + col;
        const size_t i1a = (size_t)(b * TT + row0 + 8) * CC + col;
        __half2 v0 = __floats2half2_rn(o[ni][0] * inv0, o[ni][1] * inv0);
        __half2 v1 = __floats2half2_rn(o[ni][2] * inv1, o[ni][3] * inv1);
        *(__half2*)(o16_g + i0a) = v0;
        *(__half2*)(o16_g + i1a) = v1;
    }
}

// ---------------------------------------------------------------------------
// Launch
// ---------------------------------------------------------------------------
extern "C" void kernel_launch(void* const* d_in, const int* in_sizes, int n_in,
                              void* d_out, int out_size)
{
    const float* x     = (const float*)d_in[0];
    const float* fcos  = (const float*)d_in[1];
    const float* fsin  = (const float*)d_in[2];
    const float* Wqkv  = (const float*)d_in[3];
    const float* bqkv  = (const float*)d_in[4];
    const float* Wproj = (const float*)d_in[5];
    const float* bproj = (const float*)d_in[6];
    float* out = (float*)d_out;

    __half *x16, *o16, *wq16, *wp16, *q16, *k16, *v16;
    cudaGetSymbolAddress((void**)&x16, g_x16);
    cudaGetSymbolAddress((void**)&o16, g_o16);
    cudaGetSymbolAddress((void**)&wq16, g_wq16);
    cudaGetSymbolAddress((void**)&wp16, g_wp16);
    cudaGetSymbolAddress((void**)&q16, g_q16);
    cudaGetSymbolAddress((void**)&k16, g_k16);
    cudaGetSymbolAddress((void**)&v16, g_v16);

    cudaFuncSetAttribute(hgemm, cudaFuncAttributeMaxDynamicSharedMemorySize, GSMEM);
    cudaFuncSetAttribute(hgemm_qkv, cudaFuncAttributeMaxDynamicSharedMemorySize, QKV_SMEM);
    cudaFuncSetAttribute(attn_mma, cudaFuncAttributeMaxDynamicSharedMemorySize, ATT_SMEM);

    // 0) fused prep
    prep_all<<<8192, 256>>>(x, x16, Wqkv, wq16, Wproj, wp16);

    // 1) QKV GEMM with fused bias+RoPE epilogue -> fp16 q/k/v (q in log2 units)
    {
        dim3 grid(QKVW / 128, MROWS / 128);   // (24, 32)
        hgemm_qkv<<<grid, 256, QKV_SMEM>>>(x16, wq16, bqkv, fcos, fsin,
                                           q16, k16, v16, CC);
    }
    // 2) Flash attention (base-2 softmax) -> fp16 att
    {
        dim3 grid(TT / 64, BB * HH);          // (32, 32)
        attn_mma<<<grid, 128, ATT_SMEM>>>(q16, k16, v16, o16);
    }
    // 3) out = att @ Wproj + bproj
    {
        dim3 grid(CC / 128, MROWS / 128);     // (8, 32)
        hgemm<<<grid, 256, GSMEM>>>(o16, wp16, bproj, out, MROWS, CC, CC);
    }
}